// round 3
// baseline (speedup 1.0000x reference)
#include <cuda_runtime.h>
#include <cstdint>

typedef unsigned long long u64;

#define NGEN 8192
#define NPOS 8192
#define NT   16384
#define DIM  256
#define BM   64
#define BN   64
#define NTHR 256
#define STP  66              // St2 row stride in u64 units (64 + pad)
#define TEMP_INV (-0.05f)    // -1/20

// ---------------- device scratch (no allocations allowed) ----------------
__device__ float g_tnorm[NT];

// ---------------- f32x2 helpers (FFMA2 path, sm_103a) ----------------
__device__ __forceinline__ void fma2(u64 &c, u64 a, u64 b) {
    asm("fma.rn.f32x2 %0, %1, %2, %0;" : "+l"(c) : "l"(a), "l"(b));
}
__device__ __forceinline__ float2 unpk(u64 v) {
    float2 r; asm("mov.b64 {%0, %1}, %2;" : "=f"(r.x), "=f"(r.y) : "l"(v)); return r;
}
__device__ __forceinline__ u64 dup2(float s) {
    u64 r; asm("mov.b64 %0, {%1, %1};" : "=l"(r) : "f"(s)); return r;
}

// ---------------- kernel 0: squared norms of all 16384 targets ----------------
__global__ void norm_kernel(const float* __restrict__ G, const float* __restrict__ P) {
    int warp = (blockIdx.x * blockDim.x + threadIdx.x) >> 5;
    int lane = threadIdx.x & 31;
    if (warp >= NT) return;
    const float* row = (warp < NGEN) ? (G + (size_t)warp * DIM)
                                     : (P + (size_t)(warp - NGEN) * DIM);
    float4 a = *(const float4*)(row + lane * 4);
    float4 b = *(const float4*)(row + 128 + lane * 4);
    float s = a.x*a.x + a.y*a.y + a.z*a.z + a.w*a.w
            + b.x*b.x + b.y*b.y + b.z*b.z + b.w*b.w;
#pragma unroll
    for (int o = 16; o; o >>= 1) s += __shfl_xor_sync(0xffffffffu, s, o);
    if (lane == 0) g_tnorm[warp] = s;
}

// ---------------- GEMM2 helper: acc[m][dpair] += dup(S[m][n]) * T[n][dpair] ----------------
__device__ __forceinline__ void gemm2_tile(u64 (&acc)[8][4],
                                           const float* __restrict__ Tn,
                                           const u64* __restrict__ St2,
                                           int m0b, int d0) {
#pragma unroll 2
    for (int n = 0; n < BN; ++n) {
        const float* trow = Tn + n * DIM + d0;
        u64 t0 = *(const u64*)(trow + 0);
        u64 t1 = *(const u64*)(trow + 2);
        u64 t2 = *(const u64*)(trow + 4);
        u64 t3 = *(const u64*)(trow + 6);
        const u64* srow = St2 + n * STP + m0b;
#pragma unroll
        for (int i = 0; i < 8; ++i) {
            u64 s2 = srow[i];                 // (s, s) broadcast, LDS.64
            fma2(acc[i][0], s2, t0);
            fma2(acc[i][1], s2, t1);
            fma2(acc[i][2], s2, t2);
            fma2(acc[i][3], s2, t3);
        }
    }
}

// ---------------- main fused kernel ----------------
// SMEM: Qt2[128][64] u64 | Tn[64][256] f32 | St2[64][STP] u64 | qn[64] | tnS[64] | rsred[2][64][16] | rs_s[2][64]
#define SMEM_BYTES (128*BM*8 + BN*DIM*4 + BN*STP*8 + BM*4 + BN*4 + 2*BM*16*4 + 2*BM*4)

__global__ void __launch_bounds__(NTHR, 1)
drift_main(const float* __restrict__ G, const float* __restrict__ P,
           float* __restrict__ out) {
    extern __shared__ char sm[];
    u64*   Qt2   = (u64*)sm;                       // [128][BM]  (d-pair, m)
    float* Tn    = (float*)(Qt2 + 128 * BM);       // [BN][DIM]
    u64*   St2   = (u64*)(Tn + BN * DIM);          // [BN][STP]  duplicated scores
    float* qn    = (float*)(St2 + BN * STP);       // [BM]
    float* tnS   = qn + BM;                        // [BN]
    float* rsred = tnS + BN;                       // [2][BM][16]
    float* rs_s  = rsred + 2 * BM * 16;            // [2][BM]

    const int t    = threadIdx.x;
    const int row0 = blockIdx.x * BM;
    // GEMM1 map: tx -> m (conflict-free Qt2 reads), ty -> n (broadcast Tn reads)
    const int tx = t & 15, ty = t >> 4;
    const int m0 = tx * 4, n0 = ty * 4;
    // GEMM2 map: warp -> 8 rows, lane -> 8 contiguous d
    const int mg = t >> 5, dg = t & 31;
    const int m0b = mg * 8, d0 = dg * 8;

    // Load Q transposed + d-paired: Qt2[d2][m] = (g[m][2*d2], g[m][2*d2+1])
    for (int idx = t; idx < BM * 128; idx += NTHR) {
        int n  = idx >> 7;
        int d2 = idx & 127;
        Qt2[d2 * BM + n] = *(const u64*)(G + (size_t)(row0 + n) * DIM + d2 * 2);
    }
    if (t < BM) qn[t] = g_tnorm[row0 + t];

    u64 accG[8][4], accP[8][4];
#pragma unroll
    for (int i = 0; i < 8; ++i)
#pragma unroll
        for (int p = 0; p < 4; ++p) { accG[i][p] = 0ull; accP[i][p] = 0ull; }
    float rsg[4] = {0.f, 0.f, 0.f, 0.f};
    float rsp[4] = {0.f, 0.f, 0.f, 0.f};

    for (int tile = 0; tile < NT / BN; ++tile) {
        const int  base  = tile * BN;
        const bool isGen = (base < NGEN);
        const float* src = isGen ? (G + (size_t)base * DIM)
                                 : (P + (size_t)(base - NGEN) * DIM);

        __syncthreads();   // previous GEMM2 done -> safe to overwrite Tn/tnS/St2
        for (int idx = t; idx < BN * (DIM / 4); idx += NTHR) {
            int n  = idx >> 6;
            int dq = idx & 63;
            *(float4*)(Tn + n * DIM + dq * 4) =
                *(const float4*)(src + (size_t)n * DIM + dq * 4);
        }
        if (t < BN) tnS[t] = g_tnorm[base + t];
        __syncthreads();

        // ---- GEMM1: scores S[m0..m0+3][n0..n0+3], f32x2 over d-pairs ----
        u64 c[4][4];
#pragma unroll
        for (int i = 0; i < 4; ++i)
#pragma unroll
            for (int j = 0; j < 4; ++j) c[i][j] = 0ull;

#pragma unroll 4
        for (int d2 = 0; d2 < 128; ++d2) {
            const u64* qrow = Qt2 + d2 * BM + m0;
            u64 q[4]  = { qrow[0], qrow[1], qrow[2], qrow[3] };
            u64 tt[4];
#pragma unroll
            for (int j = 0; j < 4; ++j)
                tt[j] = *(const u64*)(Tn + (n0 + j) * DIM + d2 * 2);
#pragma unroll
            for (int i = 0; i < 4; ++i)
#pragma unroll
                for (int j = 0; j < 4; ++j) fma2(c[i][j], q[i], tt[j]);
        }

        // ---- transform: dist -> exp weight, write duplicated scores ----
        const bool dtile = isGen && (base == row0);
#pragma unroll
        for (int i = 0; i < 4; ++i) {
            float rs_i = 0.f;
            float qni  = qn[m0 + i];
#pragma unroll
            for (int j = 0; j < 4; ++j) {
                float2 dv  = unpk(c[i][j]);
                float  dot = dv.x + dv.y;
                float  sq  = qni + tnS[n0 + j] - 2.0f * dot;
                float  s;
                if (sq > 0.f) s = __expf(sq * rsqrtf(sq) * TEMP_INV);
                else          s = 1.0f;
                if (dtile && (m0 + i == n0 + j)) s = 0.f;   // diag -> exp(-5e6) = 0
                St2[(n0 + j) * STP + (m0 + i)] = dup2(s);
                rs_i += s;
            }
            if (isGen) rsg[i] += rs_i; else rsp[i] += rs_i;
        }
        __syncthreads();

        // ---- GEMM2: accumulate k @ targets ----
        if (isGen) gemm2_tile(accG, Tn, St2, m0b, d0);
        else       gemm2_tile(accP, Tn, St2, m0b, d0);
    }

    // ---- reduce row sums across the 16 ty-threads per row ----
#pragma unroll
    for (int i = 0; i < 4; ++i) {
        rsred[(m0 + i) * 16 + ty]            = rsg[i];
        rsred[BM * 16 + (m0 + i) * 16 + ty]  = rsp[i];
    }
    __syncthreads();
    if (t < BM) {
        float sg = 0.f, sp = 0.f;
#pragma unroll
        for (int k = 0; k < 16; ++k) {
            sg += rsred[t * 16 + k];
            sp += rsred[BM * 16 + t * 16 + k];
        }
        rs_s[t]      = sg;
        rs_s[BM + t] = sp;
    }
    __syncthreads();

    // ---- combine and write out ----
#pragma unroll
    for (int i = 0; i < 8; ++i) {
        int   m  = m0b + i;
        float sg = rs_s[m];
        float sp = rs_s[BM + m];
        float2 p0 = unpk(accP[i][0]), p1 = unpk(accP[i][1]),
               p2 = unpk(accP[i][2]), p3 = unpk(accP[i][3]);
        float2 g0 = unpk(accG[i][0]), g1 = unpk(accG[i][1]),
               g2 = unpk(accG[i][2]), g3 = unpk(accG[i][3]);
        float4 o0, o1;
        o0.x = sg * p0.x - sp * g0.x;  o0.y = sg * p0.y - sp * g0.y;
        o0.z = sg * p1.x - sp * g1.x;  o0.w = sg * p1.y - sp * g1.y;
        o1.x = sg * p2.x - sp * g2.x;  o1.y = sg * p2.y - sp * g2.y;
        o1.z = sg * p3.x - sp * g3.x;  o1.w = sg * p3.y - sp * g3.y;
        float* orow = out + (size_t)(row0 + m) * DIM + d0;
        *(float4*)(orow)     = o0;
        *(float4*)(orow + 4) = o1;
    }
}

// ---------------- launch ----------------
extern "C" void kernel_launch(void* const* d_in, const int* in_sizes, int n_in,
                              void* d_out, int out_size) {
    const float* G = (const float*)d_in[0];   // data_generated [8192,256]
    const float* P = (const float*)d_in[1];   // data_positive  [8192,256]
    float* out = (float*)d_out;               // [8192,256]

    cudaFuncSetAttribute(drift_main, cudaFuncAttributeMaxDynamicSharedMemorySize,
                         SMEM_BYTES);

    norm_kernel<<<NT / 8, 256>>>(G, P);
    drift_main<<<NGEN / BM, NTHR, SMEM_BYTES>>>(G, P, out);
}

// round 4
// speedup vs baseline: 1.1342x; 1.1342x over previous
#include <cuda_runtime.h>
#include <cstdint>

typedef unsigned long long u64;

#define NGEN 8192
#define NPOS 8192
#define NT   16384
#define DIM  256
#define BM   64
#define BN   64
#define NTHR 512
#define TNP  264             // Tn row stride in floats (264 mod 32 = 8 -> conflict-free)
#define STP  66              // St2 row stride in u64 units
#define TEMP_INV (-0.05f)    // -1/20

// ---------------- device scratch (no allocations allowed) ----------------
__device__ float g_tnorm[NT];

// ---------------- f32x2 helpers (FFMA2 path, sm_103a) ----------------
__device__ __forceinline__ void fma2(u64 &c, u64 a, u64 b) {
    asm("fma.rn.f32x2 %0, %1, %2, %0;" : "+l"(c) : "l"(a), "l"(b));
}
__device__ __forceinline__ float2 unpk(u64 v) {
    float2 r; asm("mov.b64 {%0, %1}, %2;" : "=f"(r.x), "=f"(r.y) : "l"(v)); return r;
}
__device__ __forceinline__ u64 dup2(float s) {
    u64 r; asm("mov.b64 %0, {%1, %1};" : "=l"(r) : "f"(s)); return r;
}

// ---------------- kernel 0: squared norms of all 16384 targets ----------------
__global__ void norm_kernel(const float* __restrict__ G, const float* __restrict__ P) {
    int warp = (blockIdx.x * blockDim.x + threadIdx.x) >> 5;
    int lane = threadIdx.x & 31;
    if (warp >= NT) return;
    const float* row = (warp < NGEN) ? (G + (size_t)warp * DIM)
                                     : (P + (size_t)(warp - NGEN) * DIM);
    float4 a = *(const float4*)(row + lane * 4);
    float4 b = *(const float4*)(row + 128 + lane * 4);
    float s = a.x*a.x + a.y*a.y + a.z*a.z + a.w*a.w
            + b.x*b.x + b.y*b.y + b.z*b.z + b.w*b.w;
#pragma unroll
    for (int o = 16; o; o >>= 1) s += __shfl_xor_sync(0xffffffffu, s, o);
    if (lane == 0) g_tnorm[warp] = s;
}

// ---------------- GEMM2 helper ----------------
// warp covers 8 m-rows x one 128-float d-half; lane owns 4 floats (2 f32x2).
__device__ __forceinline__ void gemm2_tile(u64 (&acc)[8][2],
                                           const float* __restrict__ Tn,
                                           const u64* __restrict__ St2,
                                           int m0b, int d0) {
#pragma unroll 2
    for (int n = 0; n < BN; ++n) {
        ulonglong2 tv = *(const ulonglong2*)(Tn + n * TNP + d0);   // LDS.128
        const ulonglong2* srow = (const ulonglong2*)(St2 + n * STP + m0b);
        ulonglong2 s01 = srow[0];   // uniform per warp -> broadcast
        ulonglong2 s23 = srow[1];
        ulonglong2 s45 = srow[2];
        ulonglong2 s67 = srow[3];
        fma2(acc[0][0], s01.x, tv.x);  fma2(acc[0][1], s01.x, tv.y);
        fma2(acc[1][0], s01.y, tv.x);  fma2(acc[1][1], s01.y, tv.y);
        fma2(acc[2][0], s23.x, tv.x);  fma2(acc[2][1], s23.x, tv.y);
        fma2(acc[3][0], s23.y, tv.x);  fma2(acc[3][1], s23.y, tv.y);
        fma2(acc[4][0], s45.x, tv.x);  fma2(acc[4][1], s45.x, tv.y);
        fma2(acc[5][0], s45.y, tv.x);  fma2(acc[5][1], s45.y, tv.y);
        fma2(acc[6][0], s67.x, tv.x);  fma2(acc[6][1], s67.x, tv.y);
        fma2(acc[7][0], s67.y, tv.x);  fma2(acc[7][1], s67.y, tv.y);
    }
}

// ---------------- SMEM layout ----------------
// Qt2[128][64] u64 | Tn[64][TNP] f32 | St2[64][STP] u64 | qn[64] | tnS[64] | rsred[2][64][16] | rs_s[2][64]
#define SMEM_BYTES (128*BM*8 + BN*TNP*4 + BN*STP*8 + BM*4 + BN*4 + 2*BM*16*4 + 2*BM*4)

__global__ void __launch_bounds__(NTHR, 1)
drift_main(const float* __restrict__ G, const float* __restrict__ P,
           float* __restrict__ out) {
    extern __shared__ char sm[];
    u64*   Qt2   = (u64*)sm;                       // [128][BM]  (d-pair, m)
    float* Tn    = (float*)(Qt2 + 128 * BM);       // [BN][TNP]
    u64*   St2   = (u64*)(Tn + BN * TNP);          // [BN][STP]  duplicated scores
    float* qn    = (float*)(St2 + BN * STP);       // [BM]
    float* tnS   = qn + BM;                        // [BN]
    float* rsred = tnS + BN;                       // [2][BM][16]
    float* rs_s  = rsred + 2 * BM * 16;            // [2][BM]

    const int t    = threadIdx.x;
    const int w    = t >> 5;
    const int lane = t & 31;
    const int row0 = blockIdx.x * BM;

    // GEMM1 map: 16 warps = wm(4) x wn(4); warp tile 16m x 16n.
    // lane = lm(8) x ln(4); thread: 2 m-rows, 4 n-rows (consecutive-n per instr).
    const int wm = w & 3, wn = w >> 2;
    const int lm = lane & 7, ln = lane >> 3;
    const int m0 = wm * 16 + lm * 2;
    const int nb = wn * 16 + ln;            // n_j = nb + 4*j
    const int rcol = wn * 4 + ln;           // rowsum reduction column

    // GEMM2 map: 16 warps = w8(8 m-blocks of 8) x wd(2 d-halves); lane -> 4 floats.
    const int w8 = w & 7, wd = w >> 3;
    const int m0b = w8 * 8;
    const int d0  = wd * 128 + lane * 4;

    // Load Q transposed + d-paired: Qt2[d2][m] = (g[m][2*d2], g[m][2*d2+1])
    for (int idx = t; idx < BM * 128; idx += NTHR) {
        int n  = idx >> 7;
        int d2 = idx & 127;
        Qt2[d2 * BM + n] = *(const u64*)(G + (size_t)(row0 + n) * DIM + d2 * 2);
    }
    if (t < BM) qn[t] = g_tnorm[row0 + t];

    u64 accG[8][2], accP[8][2];
#pragma unroll
    for (int i = 0; i < 8; ++i) {
        accG[i][0] = 0ull; accG[i][1] = 0ull;
        accP[i][0] = 0ull; accP[i][1] = 0ull;
    }
    float rsg[2] = {0.f, 0.f};
    float rsp[2] = {0.f, 0.f};

    const u64*   qp0 = Qt2 + m0;            // q row base (step 64 per d2)
    const float* tp0 = Tn + (nb + 0)  * TNP;
    const float* tp1 = Tn + (nb + 4)  * TNP;
    const float* tp2 = Tn + (nb + 8)  * TNP;
    const float* tp3 = Tn + (nb + 12) * TNP;

    for (int tile = 0; tile < NT / BN; ++tile) {
        const int  base  = tile * BN;
        const bool isGen = (base < NGEN);
        const float* src = isGen ? (G + (size_t)base * DIM)
                                 : (P + (size_t)(base - NGEN) * DIM);

        __syncthreads();   // previous GEMM2 done -> safe to overwrite Tn/tnS/St2
        for (int idx = t; idx < BN * (DIM / 4); idx += NTHR) {
            int n  = idx >> 6;
            int dq = idx & 63;
            *(float4*)(Tn + n * TNP + dq * 4) =
                *(const float4*)(src + (size_t)n * DIM + dq * 4);
        }
        if (t < BN) tnS[t] = g_tnorm[base + t];
        __syncthreads();

        // ---- GEMM1: scores c[2m][4n], d processed in f32x2-pairs (2 d2/step) ----
        u64 c[2][4];
#pragma unroll
        for (int i = 0; i < 2; ++i)
#pragma unroll
            for (int j = 0; j < 4; ++j) c[i][j] = 0ull;

#pragma unroll 2
        for (int p = 0; p < 64; ++p) {
            ulonglong2 t0 = *(const ulonglong2*)(tp0 + p * 4);   // d2=2p (.x), 2p+1 (.y)
            ulonglong2 t1 = *(const ulonglong2*)(tp1 + p * 4);
            ulonglong2 t2 = *(const ulonglong2*)(tp2 + p * 4);
            ulonglong2 t3 = *(const ulonglong2*)(tp3 + p * 4);
            ulonglong2 qa = *(const ulonglong2*)(qp0 + (2 * p)     * BM);
            ulonglong2 qb = *(const ulonglong2*)(qp0 + (2 * p + 1) * BM);
            fma2(c[0][0], qa.x, t0.x);  fma2(c[0][1], qa.x, t1.x);
            fma2(c[0][2], qa.x, t2.x);  fma2(c[0][3], qa.x, t3.x);
            fma2(c[1][0], qa.y, t0.x);  fma2(c[1][1], qa.y, t1.x);
            fma2(c[1][2], qa.y, t2.x);  fma2(c[1][3], qa.y, t3.x);
            fma2(c[0][0], qb.x, t0.y);  fma2(c[0][1], qb.x, t1.y);
            fma2(c[0][2], qb.x, t2.y);  fma2(c[0][3], qb.x, t3.y);
            fma2(c[1][0], qb.y, t0.y);  fma2(c[1][1], qb.y, t1.y);
            fma2(c[1][2], qb.y, t2.y);  fma2(c[1][3], qb.y, t3.y);
        }

        // ---- transform: dist -> exp weight, write duplicated scores ----
        const bool dtile = isGen && (base == row0);
#pragma unroll
        for (int i = 0; i < 2; ++i) {
            float rs_i = 0.f;
            float qni  = qn[m0 + i];
#pragma unroll
            for (int j = 0; j < 4; ++j) {
                int    nj  = nb + 4 * j;
                float2 dv  = unpk(c[i][j]);
                float  dot = dv.x + dv.y;
                float  sq  = qni + tnS[nj] - 2.0f * dot;
                float  s;
                if (sq > 0.f) s = __expf(sq * rsqrtf(sq) * TEMP_INV);
                else          s = 1.0f;
                if (dtile && (m0 + i == nj)) s = 0.f;   // diag -> exp(-5e6) = 0
                St2[nj * STP + (m0 + i)] = dup2(s);
                rs_i += s;
            }
            if (isGen) rsg[i] += rs_i; else rsp[i] += rs_i;
        }
        __syncthreads();

        // ---- GEMM2: accumulate k @ targets ----
        if (isGen) gemm2_tile(accG, Tn, St2, m0b, d0);
        else       gemm2_tile(accP, Tn, St2, m0b, d0);
    }

    // ---- reduce row sums across the 16 (wn,ln) threads per row ----
#pragma unroll
    for (int i = 0; i < 2; ++i) {
        rsred[(m0 + i) * 16 + rcol]            = rsg[i];
        rsred[BM * 16 + (m0 + i) * 16 + rcol]  = rsp[i];
    }
    __syncthreads();
    if (t < BM) {
        float sg = 0.f, sp = 0.f;
#pragma unroll
        for (int k = 0; k < 16; ++k) {
            sg += rsred[t * 16 + k];
            sp += rsred[BM * 16 + t * 16 + k];
        }
        rs_s[t]      = sg;
        rs_s[BM + t] = sp;
    }
    __syncthreads();

    // ---- combine and write out ----
#pragma unroll
    for (int i = 0; i < 8; ++i) {
        int   m  = m0b + i;
        float sg = rs_s[m];
        float sp = rs_s[BM + m];
        float2 p0 = unpk(accP[i][0]), p1 = unpk(accP[i][1]);
        float2 g0 = unpk(accG[i][0]), g1 = unpk(accG[i][1]);
        float4 o;
        o.x = sg * p0.x - sp * g0.x;
        o.y = sg * p0.y - sp * g0.y;
        o.z = sg * p1.x - sp * g1.x;
        o.w = sg * p1.y - sp * g1.y;
        *(float4*)(out + (size_t)(row0 + m) * DIM + d0) = o;
    }
}

// ---------------- launch ----------------
extern "C" void kernel_launch(void* const* d_in, const int* in_sizes, int n_in,
                              void* d_out, int out_size) {
    const float* G = (const float*)d_in[0];   // data_generated [8192,256]
    const float* P = (const float*)d_in[1];   // data_positive  [8192,256]
    float* out = (float*)d_out;               // [8192,256]

    cudaFuncSetAttribute(drift_main, cudaFuncAttributeMaxDynamicSharedMemorySize,
                         SMEM_BYTES);

    norm_kernel<<<NT / 8, 256>>>(G, P);
    drift_main<<<NGEN / BM, NTHR, SMEM_BYTES>>>(G, P, out);
}